// round 7
// baseline (speedup 1.0000x reference)
#include <cuda_runtime.h>
#include <cstdint>
#include <cfloat>
#include <math.h>

#define Bc 2
#define Tc 1024
#define Dc 1024
#define Hc 16
#define DHc 64
#define Rc 32
#define Lc 2
#define FFc 4096
#define OVc 16384
#define QS 3072   // fused qkv row stride

// ---------------- static device scratch ----------------
__device__ float g_delta[Bc*Tc*Rc];
__device__ float g_cos[Bc*Tc*Rc];
__device__ float g_sin[Bc*Tc*Rc];
__device__ float g_x  [Bc*Tc*Dc];
__device__ float g_h  [Bc*Tc*Dc];
__device__ float g_qkv[Bc*Tc*QS];        // fused Q|K|V
__device__ float g_o  [Bc*Tc*Dc];
__device__ float g_ff [Bc*Tc*FFc];
__device__ float g_sc [(size_t)Bc*Hc*Tc*Tc];   // scores
__device__ float g_wqkv[Lc*Dc*QS];       // packed [D][3072] per layer
__device__ float g_bqkv[Lc*QS];

// ---------------- helpers ----------------
__device__ __forceinline__ uint32_t smem_u32(const void* p) {
    uint32_t a;
    asm("{ .reg .u64 t; cvta.to.shared.u64 t, %1; cvt.u32.u64 %0, t; }" : "=r"(a) : "l"(p));
    return a;
}
__device__ __forceinline__ float f2tf(float x) {
    uint32_t u; asm("cvt.rna.tf32.f32 %0, %1;" : "=r"(u) : "f"(x));
    return __uint_as_float(u);
}
__device__ __forceinline__ void split2(float x, uint32_t& hi, uint32_t& lo) {
    float h = f2tf(x);
    float l = f2tf(x - h);
    hi = __float_as_uint(h);
    lo = __float_as_uint(l);
}
__device__ __forceinline__ void cp16(uint32_t dst, const float* src) {
    asm volatile("cp.async.cg.shared.global [%0], [%1], 16;" :: "r"(dst), "l"(src) : "memory");
}
#define CP_COMMIT() asm volatile("cp.async.commit_group;" ::: "memory")
#define CP_WAIT1()  asm volatile("cp.async.wait_group 1;" ::: "memory")
#define CP_WAIT0()  asm volatile("cp.async.wait_group 0;" ::: "memory")

#define MMA8(d, a, b) \
    asm volatile("mma.sync.aligned.m16n8k8.row.col.f32.tf32.tf32.f32 " \
        "{%0,%1,%2,%3}, {%4,%5,%6,%7}, {%8,%9}, {%0,%1,%2,%3};" \
        : "+f"((d)[0]), "+f"((d)[1]), "+f"((d)[2]), "+f"((d)[3]) \
        : "r"((a)[0]), "r"((a)[1]), "r"((a)[2]), "r"((a)[3]), "r"((b)[0]), "r"((b)[1]))

// ================= 3xTF32 mma.sync GEMM =================
// C[M,N] = A[M,K] * B  with A K-major [M][K].
// BLAY 0 (TN): B is [N][K] K-major (scores: B = K-matrix rows).
// BLAY 1 (NN): B is [K][N] N-major (all weight GEMMs, attn*V).
// 128 x NT tiles, K-chunk 32, double-buffered cp.async.
// MODE 0: +bias(if non-null) | 1: +bias+residual | 2: gelu(+bias)
// CSKIP: skip tiles above diagonal. CKLIM: clamp K at bm+128.
template<int NT, int MODE, int BLAY, bool CSKIP, bool CKLIM>
__global__ void __launch_bounds__(256)
mma_gemm(const float* __restrict__ A, const float* __restrict__ Bt,
         const float* __restrict__ bias, const float* __restrict__ Res,
         float* __restrict__ C,
         int M, int N, int K, int lda, int ldb, int ldc,
         int H2, long long sAb, long long sAh, long long sBb, long long sBh,
         long long sCb, long long sCh)
{
    int bm = blockIdx.y * 128, bn = blockIdx.x * NT;
    if (CSKIP && bn > bm) return;

    int z = blockIdx.z;
    int zb = z / H2, zh = z % H2;
    A  += zb * sAb + zh * sAh;
    Bt += zb * sBb + zh * sBh;
    C  += zb * sCb + zh * sCh;
    const float* R0 = (MODE == 1) ? (Res + zb * sCb + zh * sCh) : nullptr;

    extern __shared__ float sm[];
    const int APITCH = 36;                       // 128 rows x 32k, pitch 36
    const int ASTG = 128 * APITCH;
    const int BP   = (BLAY == 1) ? (NT + 8) : 36;
    const int BSTG = (BLAY == 1) ? (32 * BP) : (NT * 36);
    float* Bbase = sm + 2 * ASTG;

    int tid = threadIdx.x;
    int w = tid >> 5, lane = tid & 31;
    int wm = w & 1, wn = w >> 1;                 // warp grid 2 x 4
    int g = lane >> 2, tg = lane & 3;
    const int NTILES = NT / 32;

    int Keff = K;
    if (CKLIM) { int kl = bm + 128; Keff = (kl < K) ? kl : K; }
    int NCH = Keff >> 5;                         // K-chunk 32

    float acc[4][NTILES][4];
    #pragma unroll
    for (int i = 0; i < 4; i++)
        #pragma unroll
        for (int j = 0; j < NTILES; j++)
            #pragma unroll
            for (int e = 0; e < 4; e++) acc[i][j][e] = 0.f;

    auto copy_chunk = [&](int c, int s) {
        // A: 128 rows x 32 k  (1024 cp16)
        const float* Ak = A + (size_t)bm * lda + c * 32;
        float* As = sm + s * ASTG;
        #pragma unroll
        for (int i = 0; i < 4; i++) {
            int idx = tid + i * 256;
            int row = idx >> 3, seg = idx & 7;
            cp16(smem_u32(As + row * APITCH + seg * 4), Ak + (size_t)row * lda + seg * 4);
        }
        float* Bs = Bbase + s * BSTG;
        if (BLAY == 0) {
            // B [N][K]: NT rows x 32 k
            const float* Bk = Bt + (size_t)bn * ldb + c * 32;
            #pragma unroll
            for (int i = 0; i < NT / 32; i++) {
                int idx = tid + i * 256;
                int row = idx >> 3, seg = idx & 7;
                cp16(smem_u32(Bs + row * 36 + seg * 4), Bk + (size_t)row * ldb + seg * 4);
            }
        } else {
            // B [K][N]: 32 k-rows x NT cols
            const float* Bk = Bt + (size_t)(c * 32) * ldb + bn;
            const int SPR = NT / 4;              // cp16 per row
            #pragma unroll
            for (int i = 0; i < NT / 32; i++) {
                int idx = tid + i * 256;
                int row = idx / SPR, seg = idx % SPR;
                cp16(smem_u32(Bs + row * BP + seg * 4), Bk + (size_t)row * ldb + seg * 4);
            }
        }
        CP_COMMIT();
    };

    copy_chunk(0, 0);
    if (NCH > 1) copy_chunk(1, 1);

    for (int c = 0; c < NCH; c++) {
        if (c + 1 < NCH) { CP_WAIT1(); } else { CP_WAIT0(); }
        __syncthreads();
        int s = c & 1;
        const float* Ap = sm + s * ASTG;
        const float* Bp = Bbase + s * BSTG;
        #pragma unroll
        for (int ks = 0; ks < 4; ks++) {
            uint32_t ah[4][4], al[4][4];
            #pragma unroll
            for (int mt = 0; mt < 4; mt++) {
                int r0 = wm * 64 + mt * 16 + g;
                split2(Ap[r0 * APITCH + ks * 8 + tg],           ah[mt][0], al[mt][0]);
                split2(Ap[(r0 + 8) * APITCH + ks * 8 + tg],     ah[mt][1], al[mt][1]);
                split2(Ap[r0 * APITCH + ks * 8 + tg + 4],       ah[mt][2], al[mt][2]);
                split2(Ap[(r0 + 8) * APITCH + ks * 8 + tg + 4], ah[mt][3], al[mt][3]);
            }
            uint32_t bh[NTILES][2], bl[NTILES][2];
            #pragma unroll
            for (int nt = 0; nt < NTILES; nt++) {
                int n0 = wn * (NT / 4) + nt * 8 + g;
                if (BLAY == 0) {
                    split2(Bp[n0 * 36 + ks * 8 + tg],     bh[nt][0], bl[nt][0]);
                    split2(Bp[n0 * 36 + ks * 8 + tg + 4], bh[nt][1], bl[nt][1]);
                } else {
                    split2(Bp[(ks * 8 + tg) * BP + n0],     bh[nt][0], bl[nt][0]);
                    split2(Bp[(ks * 8 + tg + 4) * BP + n0], bh[nt][1], bl[nt][1]);
                }
            }
            #pragma unroll
            for (int mt = 0; mt < 4; mt++)
                #pragma unroll
                for (int nt = 0; nt < NTILES; nt++) {
                    MMA8(acc[mt][nt], ah[mt], bl[nt]);
                    MMA8(acc[mt][nt], al[mt], bh[nt]);
                    MMA8(acc[mt][nt], ah[mt], bh[nt]);
                }
        }
        __syncthreads();
        if (c + 2 < NCH) copy_chunk(c + 2, s);
    }

    // -------- epilogue --------
    #pragma unroll
    for (int mt = 0; mt < 4; mt++) {
        #pragma unroll
        for (int nt = 0; nt < NTILES; nt++) {
            int row0 = bm + wm * 64 + mt * 16 + g;
            int col  = bn + wn * (NT / 4) + nt * 8 + tg * 2;
            #pragma unroll
            for (int half = 0; half < 2; half++) {
                int row = row0 + half * 8;
                float v0 = acc[mt][nt][half * 2 + 0];
                float v1 = acc[mt][nt][half * 2 + 1];
                if (MODE != 0 || bias) {
                    float2 bv = *(const float2*)(bias + col);
                    v0 += bv.x; v1 += bv.y;
                }
                if (MODE == 1) {
                    float2 rr = *(const float2*)(R0 + (size_t)row * ldc + col);
                    v0 += rr.x; v1 += rr.y;
                }
                if (MODE == 2) {
                    v0 = 0.5f * v0 * (1.f + erff(v0 * 0.70710678118654752f));
                    v1 = 0.5f * v1 * (1.f + erff(v1 * 0.70710678118654752f));
                }
                float2 o = {v0, v1};
                *(float2*)(C + (size_t)row * ldc + col) = o;
            }
        }
    }
}

// ---------------- pack Wq|Wk|Wv -> [D][3072], biases -> [3072] ----------------
__global__ void packqkv_kernel(const float* __restrict__ Wq,
                               const float* __restrict__ Wk,
                               const float* __restrict__ Wv,
                               float* __restrict__ out) {
    int mat = blockIdx.y, l = blockIdx.z;
    const float* W = (mat == 0) ? Wq : (mat == 1) ? Wk : Wv;
    int i = blockIdx.x * 256 + threadIdx.x;          // float4 idx over 1024*256
    int row = i >> 8, c4 = i & 255;
    float4 v = *(const float4*)(W + (size_t)l * Dc * Dc + (size_t)row * Dc + c4 * 4);
    *(float4*)(out + (size_t)l * Dc * QS + (size_t)row * QS + mat * Dc + c4 * 4) = v;
}
__global__ void packbias_kernel(const float* __restrict__ bq,
                                const float* __restrict__ bk,
                                const float* __restrict__ bv,
                                float* __restrict__ out) {
    int l = blockIdx.y;
    int i = blockIdx.x * 256 + threadIdx.x;          // 0..3071
    float v = (i < Dc) ? bq[l * Dc + i] : (i < 2 * Dc) ? bk[l * Dc + i - Dc] : bv[l * Dc + i - 2 * Dc];
    out[l * QS + i] = v;
}

// ---------------- block reductions ----------------
__device__ __forceinline__ float blockReduceSum(float v) {
    __shared__ float ws[32];
    int lane = threadIdx.x & 31, w = threadIdx.x >> 5;
    #pragma unroll
    for (int o = 16; o; o >>= 1) v += __shfl_down_sync(0xffffffffu, v, o);
    if (lane == 0) ws[w] = v;
    __syncthreads();
    int nw = blockDim.x >> 5;
    v = (threadIdx.x < nw) ? ws[threadIdx.x] : 0.f;
    if (w == 0) {
        #pragma unroll
        for (int o = 16; o; o >>= 1) v += __shfl_down_sync(0xffffffffu, v, o);
        if (lane == 0) ws[0] = v;
    }
    __syncthreads();
    float r = ws[0];
    __syncthreads();
    return r;
}
__device__ __forceinline__ float blockReduceMax(float v) {
    __shared__ float wm[32];
    int lane = threadIdx.x & 31, w = threadIdx.x >> 5;
    #pragma unroll
    for (int o = 16; o; o >>= 1) v = fmaxf(v, __shfl_down_sync(0xffffffffu, v, o));
    if (lane == 0) wm[w] = v;
    __syncthreads();
    int nw = blockDim.x >> 5;
    v = (threadIdx.x < nw) ? wm[threadIdx.x] : -FLT_MAX;
    if (w == 0) {
        #pragma unroll
        for (int o = 16; o; o >>= 1) v = fmaxf(v, __shfl_down_sync(0xffffffffu, v, o));
        if (lane == 0) wm[0] = v;
    }
    __syncthreads();
    float r = wm[0];
    __syncthreads();
    return r;
}

// ---------------- small kernels ----------------
__global__ void delta_kernel(const int* __restrict__ actions,
                             const float* __restrict__ action_emb,
                             const float* __restrict__ lie_w,
                             const float* __restrict__ lie_b,
                             float* __restrict__ delta) {
    int bt = blockIdx.x;
    __shared__ float emb[Dc];
    __shared__ float part[128];
    int a = actions[bt];
    const float* src = action_emb + (size_t)a * Dc;
    for (int i = threadIdx.x; i < Dc; i += blockDim.x) emb[i] = src[i];
    __syncthreads();
    int r = threadIdx.x & 31;
    int seg = threadIdx.x >> 5;
    float s = 0.f;
    int d0 = seg * 256;
    #pragma unroll 8
    for (int d = d0; d < d0 + 256; d++) s += emb[d] * lie_w[d * Rc + r];
    part[threadIdx.x] = s;
    __syncthreads();
    if (threadIdx.x < 32) {
        float v = part[threadIdx.x] + part[threadIdx.x + 32] +
                  part[threadIdx.x + 64] + part[threadIdx.x + 96];
        delta[(size_t)bt * Rc + threadIdx.x] = v + lie_b[threadIdx.x];
    }
}

__global__ void scan_kernel(const float* __restrict__ delta,
                            float* __restrict__ cosT, float* __restrict__ sinT) {
    int b = blockIdx.x / Rc, r = blockIdx.x % Rc;
    __shared__ float buf[2][Tc];
    int t = threadIdx.x;
    buf[0][t] = delta[((size_t)b * Tc + t) * Rc + r];
    __syncthreads();
    int src = 0;
    #pragma unroll
    for (int off = 1; off < Tc; off <<= 1) {
        float nv = buf[src][t];
        if (t >= off) nv += buf[src][t - off];
        buf[1 - src][t] = nv;
        src = 1 - src;
        __syncthreads();
    }
    float th = buf[src][t];
    size_t idx = ((size_t)b * Tc + t) * Rc + r;
    cosT[idx] = cosf(th);
    sinT[idx] = sinf(th);
}

__global__ void gather_kernel(const int* __restrict__ obs,
                              const float* __restrict__ emb,
                              float* __restrict__ x) {
    int bt = blockIdx.x;
    int o = obs[bt];
    const float4* s = (const float4*)(emb + (size_t)o * Dc);
    float4* d = (float4*)(x + (size_t)bt * Dc);
    d[threadIdx.x] = s[threadIdx.x];
}

__global__ void ln_kernel(const float* __restrict__ x,
                          const float* __restrict__ g,
                          const float* __restrict__ b,
                          float* __restrict__ out) {
    int row = blockIdx.x;
    const float4* xr = (const float4*)(x + (size_t)row * Dc);
    float4 v = xr[threadIdx.x];
    float s = v.x + v.y + v.z + v.w;
    s = blockReduceSum(s);
    float mean = s * (1.f / Dc);
    float dx = v.x - mean, dy = v.y - mean, dz = v.z - mean, dw = v.w - mean;
    float s2 = dx*dx + dy*dy + dz*dz + dw*dw;
    s2 = blockReduceSum(s2);
    float rstd = rsqrtf(s2 * (1.f / Dc) + 1e-5f);
    float4 gv = ((const float4*)g)[threadIdx.x];
    float4 bv = ((const float4*)b)[threadIdx.x];
    float4 o;
    o.x = dx * rstd * gv.x + bv.x;
    o.y = dy * rstd * gv.y + bv.y;
    o.z = dz * rstd * gv.z + bv.z;
    o.w = dw * rstd * gv.w + bv.w;
    ((float4*)(out + (size_t)row * Dc))[threadIdx.x] = o;
}

// rotate Q and K inside fused qkv buffer (stride QS)
__global__ void rope_kernel(const float* __restrict__ cosT,
                            const float* __restrict__ sinT,
                            float* __restrict__ QKV) {
    int idx = blockIdx.x * blockDim.x + threadIdx.x;
    if (idx >= Bc * Tc * Hc * Rc) return;
    int r = idx & 31;
    int h = (idx >> 5) & 15;
    int bt = idx >> 9;
    float c = cosT[(size_t)bt * Rc + r];
    float s = sinT[(size_t)bt * Rc + r];
    size_t base = (size_t)bt * QS + h * DHc + 2 * r;
    float2 q = *(float2*)(QKV + base);
    float2 k = *(float2*)(QKV + base + Dc);
    float2 qo, ko;
    qo.x = c * q.x - s * q.y;  qo.y = s * q.x + c * q.y;
    ko.x = c * k.x - s * k.y;  ko.y = s * k.x + c * k.y;
    *(float2*)(QKV + base) = qo;
    *(float2*)(QKV + base + Dc) = ko;
}

__global__ void softmax_kernel(float* __restrict__ scores) {
    int row = blockIdx.x;
    int t = row & (Tc - 1);
    float* p = scores + (size_t)row * Tc;
    int valid = t + 1;
    float4 v = ((float4*)p)[threadIdx.x];
    int base = threadIdx.x * 4;
    float vals[4] = {v.x, v.y, v.z, v.w};
    float m = -FLT_MAX;
    #pragma unroll
    for (int c = 0; c < 4; c++) {
        vals[c] = (base + c < valid) ? vals[c] * 0.125f : -FLT_MAX;
        m = fmaxf(m, vals[c]);
    }
    m = blockReduceMax(m);
    float s = 0.f;
    #pragma unroll
    for (int c = 0; c < 4; c++) {
        vals[c] = (base + c < valid) ? __expf(vals[c] - m) : 0.f;
        s += vals[c];
    }
    s = blockReduceSum(s);
    float inv = 1.f / s;
    float4 o = {vals[0]*inv, vals[1]*inv, vals[2]*inv, vals[3]*inv};
    ((float4*)p)[threadIdx.x] = o;
}

// ---------------- host launcher ----------------
static float* symaddr(const void* sym) {
    void* p = nullptr;
    cudaGetSymbolAddress(&p, sym);
    return (float*)p;
}

extern "C" void kernel_launch(void* const* d_in, const int* in_sizes, int n_in,
                              void* d_out, int out_size) {
    const int*   actions      = (const int*)  d_in[0];
    const int*   observations = (const int*)  d_in[1];
    const float* action_emb   = (const float*)d_in[2];
    const float* obs_emb      = (const float*)d_in[3];
    const float* lie_w        = (const float*)d_in[4];
    const float* lie_b        = (const float*)d_in[5];
    const float* Wq  = (const float*)d_in[6];
    const float* bq  = (const float*)d_in[7];
    const float* Wk  = (const float*)d_in[8];
    const float* bk  = (const float*)d_in[9];
    const float* Wv  = (const float*)d_in[10];
    const float* bv  = (const float*)d_in[11];
    const float* Wo  = (const float*)d_in[12];
    const float* bo  = (const float*)d_in[13];
    const float* ln1_g = (const float*)d_in[14];
    const float* ln1_b = (const float*)d_in[15];
    const float* ln2_g = (const float*)d_in[16];
    const float* ln2_b = (const float*)d_in[17];
    const float* w1  = (const float*)d_in[18];
    const float* b1  = (const float*)d_in[19];
    const float* w2  = (const float*)d_in[20];
    const float* b2  = (const float*)d_in[21];
    const float* out_g   = (const float*)d_in[22];
    const float* out_bln = (const float*)d_in[23];
    const float* out_w   = (const float*)d_in[24];
    const float* out_b   = (const float*)d_in[25];
    (void)in_sizes; (void)n_in; (void)out_size;

    float* dlt  = symaddr(g_delta);
    float* cT   = symaddr(g_cos);
    float* sT   = symaddr(g_sin);
    float* x    = symaddr(g_x);
    float* h    = symaddr(g_h);
    float* qkv  = symaddr(g_qkv);
    float* o    = symaddr(g_o);
    float* ff   = symaddr(g_ff);
    float* sc   = symaddr(g_sc);
    float* wqkv = symaddr(g_wqkv);
    float* bqkv = symaddr(g_bqkv);

    const int BT = Bc * Tc;
    const int SMTN   = (2 * 128 * 36 + 2 * 128 * 36) * 4;   // 73728
    const int SMNN   = (2 * 128 * 36 + 2 * 32 * 136) * 4;   // 71680
    const int SMNN64 = (2 * 128 * 36 + 2 * 32 * 72) * 4;    // 55296

    cudaFuncSetAttribute(mma_gemm<128,0,1,false,false>, cudaFuncAttributeMaxDynamicSharedMemorySize, SMNN);
    cudaFuncSetAttribute(mma_gemm<128,1,1,false,false>, cudaFuncAttributeMaxDynamicSharedMemorySize, SMNN);
    cudaFuncSetAttribute(mma_gemm<128,2,1,false,false>, cudaFuncAttributeMaxDynamicSharedMemorySize, SMNN);
    cudaFuncSetAttribute(mma_gemm<128,0,0,true,false>,  cudaFuncAttributeMaxDynamicSharedMemorySize, SMTN);
    cudaFuncSetAttribute(mma_gemm<64,0,1,false,true>,   cudaFuncAttributeMaxDynamicSharedMemorySize, SMNN64);

    // pack fused QKV weights + biases
    packqkv_kernel<<<dim3(1024, 3, Lc), 256>>>(Wq, Wk, Wv, wqkv);
    packbias_kernel<<<dim3(12, Lc), 256>>>(bq, bk, bv, bqkv);

    // position state
    delta_kernel<<<BT, 128>>>(actions, action_emb, lie_w, lie_b, dlt);
    scan_kernel<<<Bc * Rc, Tc>>>(dlt, cT, sT);
    gather_kernel<<<BT, 256>>>(observations, obs_emb, x);

    for (int l = 0; l < Lc; l++) {
        ln_kernel<<<BT, 256>>>(x, ln1_g + l * Dc, ln1_b + l * Dc, h);

        // fused QKV: [BT,1024] x [1024,3072]
        dim3 gQ(QS / 128, BT / 128, 1);
        mma_gemm<128,0,1,false,false><<<gQ, 256, SMNN>>>(h, wqkv + (size_t)l*Dc*QS, bqkv + l*QS, nullptr, qkv,
            BT, QS, Dc, Dc, QS, QS, 1, 0,0,0,0,0,0);

        rope_kernel<<<(Bc*Tc*Hc*Rc) / 256, 256>>>(cT, sT, qkv);

        // scores = Qr @ Kr^T (TN, causal tiles only)
        dim3 gS(Tc / 128, Tc / 128, Bc * Hc);
        mma_gemm<128,0,0,true,false><<<gS, 256, SMTN>>>(qkv, qkv + Dc, nullptr, nullptr, sc,
            Tc, Tc, DHc, QS, QS, Tc,
            Hc, (long long)Tc*QS, DHc, (long long)Tc*QS, DHc,
                (long long)Hc*Tc*Tc, (long long)Tc*Tc);

        softmax_kernel<<<Bc * Hc * Tc, 256>>>(sc);

        // o = attn @ V (NN, K clamped to diagonal)
        dim3 gA(1, Tc / 128, Bc * Hc);
        mma_gemm<64,0,1,false,true><<<gA, 256, SMNN64>>>(sc, qkv + 2*Dc, nullptr, nullptr, o,
            Tc, DHc, Tc, Tc, QS, Dc,
            Hc, (long long)Hc*Tc*Tc, (long long)Tc*Tc,
                (long long)Tc*QS, DHc,
                (long long)Tc*Dc, DHc);

        // x = x + o @ Wo + bo
        dim3 gP(Dc / 128, BT / 128, 1);
        mma_gemm<128,1,1,false,false><<<gP, 256, SMNN>>>(o, Wo + (size_t)l*Dc*Dc, bo + l*Dc, x, x,
            BT, Dc, Dc, Dc, Dc, Dc, 1, 0,0,0,0,0,0);

        ln_kernel<<<BT, 256>>>(x, ln2_g + l * Dc, ln2_b + l * Dc, h);

        dim3 gF1(FFc / 128, BT / 128, 1);
        mma_gemm<128,2,1,false,false><<<gF1, 256, SMNN>>>(h, w1 + (size_t)l*Dc*FFc, b1 + l*FFc, nullptr, ff,
            BT, FFc, Dc, Dc, FFc, FFc, 1, 0,0,0,0,0,0);
        dim3 gF2(Dc / 128, BT / 128, 1);
        mma_gemm<128,1,1,false,false><<<gF2, 256, SMNN>>>(ff, w2 + (size_t)l*FFc*Dc, b2 + l*Dc, x, x,
            BT, Dc, FFc, FFc, Dc, Dc, 1, 0,0,0,0,0,0);
    }

    ln_kernel<<<BT, 256>>>(x, out_g, out_bln, h);
    dim3 gO(OVc / 128, BT / 128, 1);
    mma_gemm<128,0,1,false,false><<<gO, 256, SMNN>>>(h, out_w, out_b, nullptr, (float*)d_out,
        BT, OVc, Dc, Dc, OVc, OVc, 1, 0,0,0,0,0,0);
}

// round 8
// speedup vs baseline: 1.5002x; 1.5002x over previous
#include <cuda_runtime.h>
#include <cstdint>
#include <cfloat>
#include <math.h>

#define Bc 2
#define Tc 1024
#define Dc 1024
#define Hc 16
#define DHc 64
#define Rc 32
#define Lc 2
#define FFc 4096
#define OVc 16384
#define QS 3072

// ---------------- static device scratch ----------------
__device__ float g_delta[Bc*Tc*Rc];
__device__ float g_cos[Bc*Tc*Rc];
__device__ float g_sin[Bc*Tc*Rc];
__device__ float g_x  [Bc*Tc*Dc];
__device__ float g_h  [Bc*Tc*Dc];
__device__ float g_qkv[Bc*Tc*QS];              // fused Q|K|V (stride 3072)
__device__ float g_vt [Bc*Hc*DHc*Tc];
__device__ float g_o  [Bc*Tc*Dc];
__device__ float g_ff [Bc*Tc*FFc];
__device__ float g_sc [(size_t)Bc*Hc*Tc*Tc];   // scores
__device__ float g_wT [40*Dc*Dc];              // transposed weights
__device__ float g_bqkv[Lc*QS];

// layer block in g_wT: [qkvT(3DD), WoT(DD), w1T(4DD), w2T(4DD)] = 12*DD
#define WT_L(l)   ((size_t)(l) * 12 * Dc * Dc)
#define WT_OUT    ((size_t)24 * Dc * Dc)

// ---------------- helpers ----------------
__device__ __forceinline__ uint32_t smem_u32(const void* p) {
    uint32_t a;
    asm("{ .reg .u64 t; cvta.to.shared.u64 t, %1; cvt.u32.u64 %0, t; }" : "=r"(a) : "l"(p));
    return a;
}
__device__ __forceinline__ float f2tf(float x) {
    uint32_t u; asm("cvt.rna.tf32.f32 %0, %1;" : "=r"(u) : "f"(x));
    return __uint_as_float(u);
}
__device__ __forceinline__ void split2(float x, uint32_t& hi, uint32_t& lo) {
    float h = f2tf(x);
    float l = f2tf(x - h);
    hi = __float_as_uint(h);
    lo = __float_as_uint(l);
}
__device__ __forceinline__ void cp16(uint32_t dst, const float* src) {
    asm volatile("cp.async.cg.shared.global [%0], [%1], 16;" :: "r"(dst), "l"(src) : "memory");
}
#define CP_COMMIT() asm volatile("cp.async.commit_group;" ::: "memory")
#define CP_WAIT1()  asm volatile("cp.async.wait_group 1;" ::: "memory")
#define CP_WAIT0()  asm volatile("cp.async.wait_group 0;" ::: "memory")

#define MMA8(d, a, b) \
    asm volatile("mma.sync.aligned.m16n8k8.row.col.f32.tf32.tf32.f32 " \
        "{%0,%1,%2,%3}, {%4,%5,%6,%7}, {%8,%9}, {%0,%1,%2,%3};" \
        : "+f"((d)[0]), "+f"((d)[1]), "+f"((d)[2]), "+f"((d)[3]) \
        : "r"((a)[0]), "r"((a)[1]), "r"((a)[2]), "r"((a)[3]), "r"((b)[0]), "r"((b)[1]))

// ================= 3xTF32 mma.sync GEMM (R5-validated core) =================
// C[M,N] = A[M,K] * Bt[N,K]^T  (both K-major, raw fp32 inputs)
// 128 x NT tiles, K-chunk 16, double-buffered cp.async pipeline.
// MODE 0: +bias(if non-null) | 1: +bias+residual | 2: gelu(+bias)
// CSKIP: skip tiles strictly above diagonal. CKLIM: clamp K at bm+128.
template<int NT, int MODE, bool CSKIP, bool CKLIM>
__global__ void __launch_bounds__(256)
mma_gemm(const float* __restrict__ A, const float* __restrict__ Bt,
         const float* __restrict__ bias, const float* __restrict__ Res,
         float* __restrict__ C,
         int M, int N, int K, int lda, int ldb, int ldc,
         int H2, long long sAb, long long sAh, long long sBb, long long sBh,
         long long sCb, long long sCh)
{
    int bm = blockIdx.y * 128, bn = blockIdx.x * NT;
    if (CSKIP && bn > bm) return;

    int z = blockIdx.z;
    int zb = z / H2, zh = z % H2;
    A  += zb * sAb + zh * sAh;
    Bt += zb * sBb + zh * sBh;
    C  += zb * sCb + zh * sCh;
    const float* R0 = (MODE == 1) ? (Res + zb * sCb + zh * sCh) : nullptr;

    extern __shared__ float sm[];
    const int ASTG = 128 * 20;
    const int BSTG = NT * 20;
    float* Bbase = sm + 2 * ASTG;

    int tid = threadIdx.x;
    int w = tid >> 5, lane = tid & 31;
    int wm = w & 1, wn = w >> 1;
    int g = lane >> 2, tg = lane & 3;
    const int NTILES = NT / 32;

    int Keff = K;
    if (CKLIM) { int kl = bm + 128; Keff = (kl < K) ? kl : K; }
    int NCH = Keff >> 4;

    float acc[4][NTILES][4];
    #pragma unroll
    for (int i = 0; i < 4; i++)
        #pragma unroll
        for (int j = 0; j < NTILES; j++)
            #pragma unroll
            for (int e = 0; e < 4; e++) acc[i][j][e] = 0.f;

    auto copy_chunk = [&](int c, int s) {
        const float* Ak = A + (size_t)bm * lda + c * 16;
        float* As = sm + s * ASTG;
        #pragma unroll
        for (int i = 0; i < 2; i++) {
            int idx = tid + i * 256;
            int row = idx >> 2, seg = idx & 3;
            cp16(smem_u32(As + row * 20 + seg * 4), Ak + (size_t)row * lda + seg * 4);
        }
        const float* Bk = Bt + (size_t)bn * ldb + c * 16;
        float* Bs = Bbase + s * BSTG;
        #pragma unroll
        for (int i = 0; i < NT / 64; i++) {
            int idx = tid + i * 256;
            int row = idx >> 2, seg = idx & 3;
            cp16(smem_u32(Bs + row * 20 + seg * 4), Bk + (size_t)row * ldb + seg * 4);
        }
        CP_COMMIT();
    };

    copy_chunk(0, 0);
    copy_chunk(1, 1);

    for (int c = 0; c < NCH; c++) {
        if (c + 1 < NCH) { CP_WAIT1(); } else { CP_WAIT0(); }
        __syncthreads();
        int s = c & 1;
        const float* Ap = sm + s * ASTG;
        const float* Bp = Bbase + s * BSTG;
        #pragma unroll
        for (int ks = 0; ks < 2; ks++) {
            uint32_t ah[4][4], al[4][4];
            #pragma unroll
            for (int mt = 0; mt < 4; mt++) {
                int r0 = wm * 64 + mt * 16 + g;
                split2(Ap[r0 * 20 + ks * 8 + tg],           ah[mt][0], al[mt][0]);
                split2(Ap[(r0 + 8) * 20 + ks * 8 + tg],     ah[mt][1], al[mt][1]);
                split2(Ap[r0 * 20 + ks * 8 + tg + 4],       ah[mt][2], al[mt][2]);
                split2(Ap[(r0 + 8) * 20 + ks * 8 + tg + 4], ah[mt][3], al[mt][3]);
            }
            uint32_t bh[NTILES][2], bl[NTILES][2];
            #pragma unroll
            for (int nt = 0; nt < NTILES; nt++) {
                int n0 = wn * (NT / 4) + nt * 8 + g;
                split2(Bp[n0 * 20 + ks * 8 + tg],     bh[nt][0], bl[nt][0]);
                split2(Bp[n0 * 20 + ks * 8 + tg + 4], bh[nt][1], bl[nt][1]);
            }
            #pragma unroll
            for (int mt = 0; mt < 4; mt++)
                #pragma unroll
                for (int nt = 0; nt < NTILES; nt++) {
                    MMA8(acc[mt][nt], ah[mt], bl[nt]);
                    MMA8(acc[mt][nt], al[mt], bh[nt]);
                    MMA8(acc[mt][nt], ah[mt], bh[nt]);
                }
        }
        __syncthreads();
        if (c + 2 < NCH) copy_chunk(c + 2, s);
    }

    // -------- epilogue --------
    #pragma unroll
    for (int mt = 0; mt < 4; mt++) {
        #pragma unroll
        for (int nt = 0; nt < NTILES; nt++) {
            int row0 = bm + wm * 64 + mt * 16 + g;
            int col  = bn + wn * (NT / 4) + nt * 8 + tg * 2;
            #pragma unroll
            for (int half = 0; half < 2; half++) {
                int row = row0 + half * 8;
                float v0 = acc[mt][nt][half * 2 + 0];
                float v1 = acc[mt][nt][half * 2 + 1];
                if (MODE != 0 || bias) {
                    float2 bv = *(const float2*)(bias + col);
                    v0 += bv.x; v1 += bv.y;
                }
                if (MODE == 1) {
                    float2 rr = *(const float2*)(R0 + (size_t)row * ldc + col);
                    v0 += rr.x; v1 += rr.y;
                }
                if (MODE == 2) {
                    v0 = 0.5f * v0 * (1.f + erff(v0 * 0.70710678118654752f));
                    v1 = 0.5f * v1 * (1.f + erff(v1 * 0.70710678118654752f));
                }
                float2 o = {v0, v1};
                *(float2*)(C + (size_t)row * ldc + col) = o;
            }
        }
    }
}

// ---------------- vectorized transpose: in[rows][cols] -> out[cols][rows] ----------------
// block (8,32), grid (cols/32, rows/32); float4 on both global sides.
__global__ void transpose_kernel(const float* __restrict__ in, float* __restrict__ out,
                                 int rows, int cols) {
    __shared__ float tile[32][33];
    int c0 = blockIdx.x * 32, r0 = blockIdx.y * 32;
    int x = threadIdx.x, y = threadIdx.y;
    float4 v = *(const float4*)(in + (size_t)(r0 + y) * cols + c0 + 4 * x);
    tile[y][4*x+0] = v.x; tile[y][4*x+1] = v.y; tile[y][4*x+2] = v.z; tile[y][4*x+3] = v.w;
    __syncthreads();
    float4 o;
    o.x = tile[4*x+0][y]; o.y = tile[4*x+1][y]; o.z = tile[4*x+2][y]; o.w = tile[4*x+3][y];
    *(float4*)(out + (size_t)(c0 + y) * rows + r0 + 4 * x) = o;
}

// V inside qkv -> vt[(b*H+h)*64+d][t]   (block (8,32), grid (Tc/32, 2, B*H))
__global__ void vtrans_kernel(const float* __restrict__ qkv, float* __restrict__ vt) {
    __shared__ float tile[32][33];
    int z = blockIdx.z, b = z >> 4, h = z & 15;
    int t0 = blockIdx.x * 32, d0 = blockIdx.y * 32;
    int x = threadIdx.x, y = threadIdx.y;
    float4 v = *(const float4*)(qkv + (size_t)(b * Tc + t0 + y) * QS + 2 * Dc + h * DHc + d0 + 4 * x);
    tile[y][4*x+0] = v.x; tile[y][4*x+1] = v.y; tile[y][4*x+2] = v.z; tile[y][4*x+3] = v.w;
    __syncthreads();
    float4 o;
    o.x = tile[4*x+0][y]; o.y = tile[4*x+1][y]; o.z = tile[4*x+2][y]; o.w = tile[4*x+3][y];
    *(float4*)(vt + ((size_t)z * DHc + d0 + y) * Tc + t0 + 4 * x) = o;
}

// pack biases bq|bk|bv -> [L][3072]
__global__ void packbias_kernel(const float* __restrict__ bq,
                                const float* __restrict__ bk,
                                const float* __restrict__ bv,
                                float* __restrict__ out) {
    int l = blockIdx.y;
    int i = blockIdx.x * 256 + threadIdx.x;
    float v = (i < Dc) ? bq[l * Dc + i] : (i < 2 * Dc) ? bk[l * Dc + i - Dc] : bv[l * Dc + i - 2 * Dc];
    out[l * QS + i] = v;
}

// ---------------- block reductions ----------------
__device__ __forceinline__ float blockReduceSum(float v) {
    __shared__ float ws[32];
    int lane = threadIdx.x & 31, w = threadIdx.x >> 5;
    #pragma unroll
    for (int o = 16; o; o >>= 1) v += __shfl_down_sync(0xffffffffu, v, o);
    if (lane == 0) ws[w] = v;
    __syncthreads();
    int nw = blockDim.x >> 5;
    v = (threadIdx.x < nw) ? ws[threadIdx.x] : 0.f;
    if (w == 0) {
        #pragma unroll
        for (int o = 16; o; o >>= 1) v += __shfl_down_sync(0xffffffffu, v, o);
        if (lane == 0) ws[0] = v;
    }
    __syncthreads();
    float r = ws[0];
    __syncthreads();
    return r;
}
__device__ __forceinline__ float blockReduceMax(float v) {
    __shared__ float wm[32];
    int lane = threadIdx.x & 31, w = threadIdx.x >> 5;
    #pragma unroll
    for (int o = 16; o; o >>= 1) v = fmaxf(v, __shfl_down_sync(0xffffffffu, v, o));
    if (lane == 0) wm[w] = v;
    __syncthreads();
    int nw = blockDim.x >> 5;
    v = (threadIdx.x < nw) ? wm[threadIdx.x] : -FLT_MAX;
    if (w == 0) {
        #pragma unroll
        for (int o = 16; o; o >>= 1) v = fmaxf(v, __shfl_down_sync(0xffffffffu, v, o));
        if (lane == 0) wm[0] = v;
    }
    __syncthreads();
    float r = wm[0];
    __syncthreads();
    return r;
}

// ---------------- small kernels ----------------
__global__ void delta_kernel(const int* __restrict__ actions,
                             const float* __restrict__ action_emb,
                             const float* __restrict__ lie_w,
                             const float* __restrict__ lie_b,
                             float* __restrict__ delta) {
    int bt = blockIdx.x;
    __shared__ float emb[Dc];
    __shared__ float part[128];
    int a = actions[bt];
    const float* src = action_emb + (size_t)a * Dc;
    for (int i = threadIdx.x; i < Dc; i += blockDim.x) emb[i] = src[i];
    __syncthreads();
    int r = threadIdx.x & 31;
    int seg = threadIdx.x >> 5;
    float s = 0.f;
    int d0 = seg * 256;
    #pragma unroll 8
    for (int d = d0; d < d0 + 256; d++) s += emb[d] * lie_w[d * Rc + r];
    part[threadIdx.x] = s;
    __syncthreads();
    if (threadIdx.x < 32) {
        float v = part[threadIdx.x] + part[threadIdx.x + 32] +
                  part[threadIdx.x + 64] + part[threadIdx.x + 96];
        delta[(size_t)bt * Rc + threadIdx.x] = v + lie_b[threadIdx.x];
    }
}

__global__ void scan_kernel(const float* __restrict__ delta,
                            float* __restrict__ cosT, float* __restrict__ sinT) {
    int b = blockIdx.x / Rc, r = blockIdx.x % Rc;
    __shared__ float buf[2][Tc];
    int t = threadIdx.x;
    buf[0][t] = delta[((size_t)b * Tc + t) * Rc + r];
    __syncthreads();
    int src = 0;
    #pragma unroll
    for (int off = 1; off < Tc; off <<= 1) {
        float nv = buf[src][t];
        if (t >= off) nv += buf[src][t - off];
        buf[1 - src][t] = nv;
        src = 1 - src;
        __syncthreads();
    }
    float th = buf[src][t];
    size_t idx = ((size_t)b * Tc + t) * Rc + r;
    cosT[idx] = cosf(th);
    sinT[idx] = sinf(th);
}

__global__ void gather_kernel(const int* __restrict__ obs,
                              const float* __restrict__ emb,
                              float* __restrict__ x) {
    int bt = blockIdx.x;
    int o = obs[bt];
    const float4* s = (const float4*)(emb + (size_t)o * Dc);
    float4* d = (float4*)(x + (size_t)bt * Dc);
    d[threadIdx.x] = s[threadIdx.x];
}

__global__ void ln_kernel(const float* __restrict__ x,
                          const float* __restrict__ g,
                          const float* __restrict__ b,
                          float* __restrict__ out) {
    int row = blockIdx.x;
    const float4* xr = (const float4*)(x + (size_t)row * Dc);
    float4 v = xr[threadIdx.x];
    float s = v.x + v.y + v.z + v.w;
    s = blockReduceSum(s);
    float mean = s * (1.f / Dc);
    float dx = v.x - mean, dy = v.y - mean, dz = v.z - mean, dw = v.w - mean;
    float s2 = dx*dx + dy*dy + dz*dz + dw*dw;
    s2 = blockReduceSum(s2);
    float rstd = rsqrtf(s2 * (1.f / Dc) + 1e-5f);
    float4 gv = ((const float4*)g)[threadIdx.x];
    float4 bv = ((const float4*)b)[threadIdx.x];
    float4 o;
    o.x = dx * rstd * gv.x + bv.x;
    o.y = dy * rstd * gv.y + bv.y;
    o.z = dz * rstd * gv.z + bv.z;
    o.w = dw * rstd * gv.w + bv.w;
    ((float4*)(out + (size_t)row * Dc))[threadIdx.x] = o;
}

// rotate Q and K inside fused qkv buffer (stride QS)
__global__ void rope_kernel(const float* __restrict__ cosT,
                            const float* __restrict__ sinT,
                            float* __restrict__ QKV) {
    int idx = blockIdx.x * blockDim.x + threadIdx.x;
    if (idx >= Bc * Tc * Hc * Rc) return;
    int r = idx & 31;
    int h = (idx >> 5) & 15;
    int bt = idx >> 9;
    float c = cosT[(size_t)bt * Rc + r];
    float s = sinT[(size_t)bt * Rc + r];
    size_t base = (size_t)bt * QS + h * DHc + 2 * r;
    float2 q = *(float2*)(QKV + base);
    float2 k = *(float2*)(QKV + base + Dc);
    float2 qo, ko;
    qo.x = c * q.x - s * q.y;  qo.y = s * q.x + c * q.y;
    ko.x = c * k.x - s * k.y;  ko.y = s * k.x + c * k.y;
    *(float2*)(QKV + base) = qo;
    *(float2*)(QKV + base + Dc) = ko;
}

// causal softmax: load only <= diagonal, store up to end of 128-tile containing diagonal
__global__ void softmax_kernel(float* __restrict__ scores) {
    int row = blockIdx.x;
    int t = row & (Tc - 1);
    float* p = scores + (size_t)row * Tc;
    int valid = t + 1;
    int lastStore = ((t >> 7) + 1) << 7;     // round up to 128
    int base = threadIdx.x * 4;
    float vals[4] = {0.f, 0.f, 0.f, 0.f};
    if (base < valid) {
        float4 v = ((float4*)p)[threadIdx.x];
        vals[0] = v.x; vals[1] = v.y; vals[2] = v.z; vals[3] = v.w;
    }
    float m = -FLT_MAX;
    #pragma unroll
    for (int c = 0; c < 4; c++) {
        vals[c] = (base + c < valid) ? vals[c] * 0.125f : -FLT_MAX;
        m = fmaxf(m, vals[c]);
    }
    m = blockReduceMax(m);
    float s = 0.f;
    #pragma unroll
    for (int c = 0; c < 4; c++) {
        vals[c] = (base + c < valid) ? __expf(vals[c] - m) : 0.f;
        s += vals[c];
    }
    s = blockReduceSum(s);
    float inv = 1.f / s;
    if (base < lastStore) {
        float4 o = {vals[0]*inv, vals[1]*inv, vals[2]*inv, vals[3]*inv};
        ((float4*)p)[threadIdx.x] = o;
    }
}

// ---------------- host launcher ----------------
static float* symaddr(const void* sym) {
    void* p = nullptr;
    cudaGetSymbolAddress(&p, sym);
    return (float*)p;
}

extern "C" void kernel_launch(void* const* d_in, const int* in_sizes, int n_in,
                              void* d_out, int out_size) {
    const int*   actions      = (const int*)  d_in[0];
    const int*   observations = (const int*)  d_in[1];
    const float* action_emb   = (const float*)d_in[2];
    const float* obs_emb      = (const float*)d_in[3];
    const float* lie_w        = (const float*)d_in[4];
    const float* lie_b        = (const float*)d_in[5];
    const float* Wq  = (const float*)d_in[6];
    const float* bq  = (const float*)d_in[7];
    const float* Wk  = (const float*)d_in[8];
    const float* bk  = (const float*)d_in[9];
    const float* Wv  = (const float*)d_in[10];
    const float* bv  = (const float*)d_in[11];
    const float* Wo  = (const float*)d_in[12];
    const float* bo  = (const float*)d_in[13];
    const float* ln1_g = (const float*)d_in[14];
    const float* ln1_b = (const float*)d_in[15];
    const float* ln2_g = (const float*)d_in[16];
    const float* ln2_b = (const float*)d_in[17];
    const float* w1  = (const float*)d_in[18];
    const float* b1  = (const float*)d_in[19];
    const float* w2  = (const float*)d_in[20];
    const float* b2  = (const float*)d_in[21];
    const float* out_g   = (const float*)d_in[22];
    const float* out_bln = (const float*)d_in[23];
    const float* out_w   = (const float*)d_in[24];
    const float* out_b   = (const float*)d_in[25];
    (void)in_sizes; (void)n_in; (void)out_size;

    float* dlt  = symaddr(g_delta);
    float* cT   = symaddr(g_cos);
    float* sT   = symaddr(g_sin);
    float* x    = symaddr(g_x);
    float* h    = symaddr(g_h);
    float* qkv  = symaddr(g_qkv);
    float* vt   = symaddr(g_vt);
    float* o    = symaddr(g_o);
    float* ff   = symaddr(g_ff);
    float* sc   = symaddr(g_sc);
    float* wT   = symaddr(g_wT);
    float* bqkv = symaddr(g_bqkv);

    const int BT = Bc * Tc;
    const int SM128 = (2 * 128 * 20 + 2 * 128 * 20) * 4;   // 40960
    const int SM64  = (2 * 128 * 20 + 2 * 64 * 20) * 4;    // 30720

    dim3 tb(8, 32);
    // weight transposes into [N][K] layouts (qkv packed contiguously)
    for (int l = 0; l < Lc; l++) {
        size_t base = WT_L(l);
        transpose_kernel<<<dim3(32, 32), tb>>>(Wq + (size_t)l*Dc*Dc, wT + base + 0*Dc*Dc, Dc, Dc);
        transpose_kernel<<<dim3(32, 32), tb>>>(Wk + (size_t)l*Dc*Dc, wT + base + 1*Dc*Dc, Dc, Dc);
        transpose_kernel<<<dim3(32, 32), tb>>>(Wv + (size_t)l*Dc*Dc, wT + base + 2*Dc*Dc, Dc, Dc);
        transpose_kernel<<<dim3(32, 32), tb>>>(Wo + (size_t)l*Dc*Dc, wT + base + 3*Dc*Dc, Dc, Dc);
        transpose_kernel<<<dim3(128,32), tb>>>(w1 + (size_t)l*Dc*FFc, wT + base + 4*(size_t)Dc*Dc, Dc, FFc);
        transpose_kernel<<<dim3(32,128), tb>>>(w2 + (size_t)l*FFc*Dc, wT + base + 8*(size_t)Dc*Dc, FFc, Dc);
    }
    transpose_kernel<<<dim3(512, 32), tb>>>(out_w, wT + WT_OUT, Dc, OVc);
    packbias_kernel<<<dim3(12, Lc), 256>>>(bq, bk, bv, bqkv);

    // position state
    delta_kernel<<<BT, 128>>>(actions, action_emb, lie_w, lie_b, dlt);
    scan_kernel<<<Bc * Rc, Tc>>>(dlt, cT, sT);
    gather_kernel<<<BT, 256>>>(observations, obs_emb, x);

    for (int l = 0; l < Lc; l++) {
        size_t wb = WT_L(l);
        ln_kernel<<<BT, 256>>>(x, ln1_g + l * Dc, ln1_b + l * Dc, h);

        // fused QKV: [BT,1024] x [3072,1024]^T -> qkv (stride 3072)
        dim3 gQ(QS / 128, BT / 128, 1);
        mma_gemm<128,0,false,false><<<gQ, 256, SM128>>>(h, wT + wb, bqkv + l*QS, nullptr, qkv,
            BT, QS, Dc, Dc, Dc, QS, 1, 0,0,0,0,0,0);

        rope_kernel<<<(Bc*Tc*Hc*Rc) / 256, 256>>>(cT, sT, qkv);
        vtrans_kernel<<<dim3(Tc/32, 2, Bc*Hc), tb>>>(qkv, vt);

        // scores = Qr @ Kr^T (causal tiles only)
        dim3 gS(Tc / 128, Tc / 128, Bc * Hc);
        mma_gemm<128,0,true,false><<<gS, 256, SM128>>>(qkv, qkv + Dc, nullptr, nullptr, sc,
            Tc, Tc, DHc, QS, QS, Tc,
            Hc, (long long)Tc*QS, DHc, (long long)Tc*QS, DHc,
                (long long)Hc*Tc*Tc, (long long)Tc*Tc);

        softmax_kernel<<<Bc * Hc * Tc, 256>>>(sc);

        // o = attn @ V (K clamped to diagonal)
        dim3 gA(1, Tc / 128, Bc * Hc);
        mma_gemm<64,0,false,true><<<gA, 256, SM64>>>(sc, vt, nullptr, nullptr, o,
            Tc, DHc, Tc, Tc, Tc, Dc,
            Hc, (long long)Hc*Tc*Tc, (long long)Tc*Tc,
                (long long)Hc*DHc*Tc, (long long)DHc*Tc,
                (long long)Tc*Dc, (long long)DHc);

        // x = x + o @ Wo + bo
        dim3 gP(Dc / 128, BT / 128, 1);
        mma_gemm<128,1,false,false><<<gP, 256, SM128>>>(o, wT + wb + 3*Dc*Dc, bo + l*Dc, x, x,
            BT, Dc, Dc, Dc, Dc, Dc, 1, 0,0,0,0,0,0);

        ln_kernel<<<BT, 256>>>(x, ln2_g + l * Dc, ln2_b + l * Dc, h);

        dim3 gF1(FFc / 128, BT / 128, 1);
        mma_gemm<128,2,false,false><<<gF1, 256, SM128>>>(h, wT + wb + 4*(size_t)Dc*Dc, b1 + l*FFc, nullptr, ff,
            BT, FFc, Dc, Dc, Dc, FFc, 1, 0,0,0,0,0,0);
        dim3 gF2(Dc / 128, BT / 128, 1);
        mma_gemm<128,1,false,false><<<gF2, 256, SM128>>>(ff, wT + wb + 8*(size_t)Dc*Dc, b2 + l*Dc, x, x,
            BT, Dc, FFc, FFc, FFc, Dc, 1, 0,0,0,0,0,0);
    }

    ln_kernel<<<BT, 256>>>(x, out_g, out_bln, h);
    dim3 gO(OVc / 128, BT / 128, 1);
    mma_gemm<128,0,false,false><<<gO, 256, SM128>>>(h, wT + WT_OUT, out_b, nullptr, (float*)d_out,
        BT, OVc, Dc, Dc, Dc, OVc, 1, 0,0,0,0,0,0);
}

// round 9
// speedup vs baseline: 2.1814x; 1.4541x over previous
#include <cuda_runtime.h>
#include <cuda_bf16.h>
#include <cstdint>
#include <cfloat>
#include <math.h>

#define Bc 2
#define Tc 1024
#define Dc 1024
#define Hc 16
#define DHc 64
#define Rc 32
#define Lc 2
#define FFc 4096
#define OVc 16384
#define QS 3072
#define BT (Bc*Tc)
#define DD (Dc*Dc)

// ---------------- static device scratch ----------------
__device__ float g_delta[Bc*Tc*Rc];
__device__ float g_cos[Bc*Tc*Rc];
__device__ float g_sin[Bc*Tc*Rc];
__device__ float g_x  [BT*Dc];
__device__ float g_qkv[BT*QS];
__device__ float g_sc [(size_t)Bc*Hc*Tc*Tc];     // fp32 scores (GEMM out -> softmax in)

// packed bf16x2 hi/lo operand arrays (pair = 2 consecutive K elements)
__device__ uint32_t g_hhi[BT*512],  g_hlo[BT*512];      // ln outputs
__device__ uint32_t g_qhi[BT*512],  g_qlo[BT*512];      // rotated Q
__device__ uint32_t g_khi[BT*512],  g_klo[BT*512];      // rotated K
__device__ uint32_t g_vthi[Bc*Hc*DHc*512], g_vtlo[Bc*Hc*DHc*512]; // V^T
__device__ uint32_t g_schi[(size_t)Bc*Hc*Tc*512], g_sclo[(size_t)Bc*Hc*Tc*512];
__device__ uint32_t g_ohi[BT*512],  g_olo[BT*512];      // attn out
__device__ uint32_t g_ffhi[BT*2048], g_fflo[BT*2048];   // gelu out
__device__ uint32_t g_whi[20*DD], g_wlo[20*DD];         // all weights, transposed+split
__device__ float    g_bqkv[Lc*QS];

// weight pair-offsets inside g_whi/g_wlo
#define P_QKV 0
#define P_WO  ((size_t)3072*512)
#define P_W1  (P_WO + (size_t)1024*512)
#define P_W2  (P_W1 + (size_t)4096*512)
#define PL_SZ (P_W2 + (size_t)1024*2048)
#define P_OUT (2*PL_SZ)
#define WPL(l) ((size_t)(l)*PL_SZ)

// ---------------- helpers ----------------
__device__ __forceinline__ uint32_t smem_u32(const void* p) {
    uint32_t a;
    asm("{ .reg .u64 t; cvta.to.shared.u64 t, %1; cvt.u32.u64 %0, t; }" : "=r"(a) : "l"(p));
    return a;
}
// split (x0,x1) into packed bf16x2 hi and lo (x ~= hi + lo per element)
__device__ __forceinline__ void bsplit2(float x0, float x1, uint32_t& hi, uint32_t& lo) {
    unsigned short h0 = __bfloat16_as_ushort(__float2bfloat16_rn(x0));
    unsigned short h1 = __bfloat16_as_ushort(__float2bfloat16_rn(x1));
    float r0 = x0 - __uint_as_float(((uint32_t)h0) << 16);
    float r1 = x1 - __uint_as_float(((uint32_t)h1) << 16);
    unsigned short l0 = __bfloat16_as_ushort(__float2bfloat16_rn(r0));
    unsigned short l1 = __bfloat16_as_ushort(__float2bfloat16_rn(r1));
    hi = ((uint32_t)h1 << 16) | h0;
    lo = ((uint32_t)l1 << 16) | l0;
}
__device__ __forceinline__ void cp16(uint32_t dst, const void* src) {
    asm volatile("cp.async.cg.shared.global [%0], [%1], 16;" :: "r"(dst), "l"(src) : "memory");
}
#define CP_COMMIT() asm volatile("cp.async.commit_group;" ::: "memory")
#define CP_WAIT1()  asm volatile("cp.async.wait_group 1;" ::: "memory")
#define CP_WAIT0()  asm volatile("cp.async.wait_group 0;" ::: "memory")

#define MMA16(d, a, b) \
    asm volatile("mma.sync.aligned.m16n8k16.row.col.f32.bf16.bf16.f32 " \
        "{%0,%1,%2,%3}, {%4,%5,%6,%7}, {%8,%9}, {%0,%1,%2,%3};" \
        : "+f"((d)[0]), "+f"((d)[1]), "+f"((d)[2]), "+f"((d)[3]) \
        : "r"((a)[0]), "r"((a)[1]), "r"((a)[2]), "r"((a)[3]), "r"((b)[0]), "r"((b)[1]))

// ================= 3xBF16 mma.sync GEMM (pre-split operands) =================
// C[M,N] = A[M,K] * Bt[N,K]^T, A/B given as packed bf16x2 hi/lo arrays,
// strides in PAIR units. 128 x NT tiles, K-chunk 16, double-buffered cp.async.
// MODE 0: fp32 out (+bias if non-null) | 1: fp32 +bias+residual
//      2: packed gelu(+bias) out      | 3: packed plain out
// CSKIP: skip tiles above diagonal. CKLIM: clamp K at bm+128.
template<int NT, int MODE, bool CSKIP, bool CKLIM>
__global__ void __launch_bounds__(256)
mma_gemm(const uint32_t* __restrict__ AhG, const uint32_t* __restrict__ AlG,
         const uint32_t* __restrict__ BhG, const uint32_t* __restrict__ BlG,
         const float* __restrict__ bias, const float* __restrict__ Res,
         float* __restrict__ C, uint32_t* __restrict__ Chi, uint32_t* __restrict__ Clo,
         int M, int N, int K, int ldaP, int ldbP, int ldc,
         int H2, long long sAb, long long sAh, long long sBb, long long sBh,
         long long sCb, long long sCh)
{
    int bm = blockIdx.y * 128, bn = blockIdx.x * NT;
    if (CSKIP && bn > bm) return;

    int z = blockIdx.z;
    int zb = z / H2, zh = z % H2;
    AhG += zb * sAb + zh * sAh;  AlG += zb * sAb + zh * sAh;
    BhG += zb * sBb + zh * sBh;  BlG += zb * sBb + zh * sBh;
    const float* R0 = nullptr;
    if (MODE == 0 || MODE == 1) {
        C += zb * sCb + zh * sCh;
        if (MODE == 1) R0 = Res + zb * sCb + zh * sCh;
    } else {
        Chi += zb * sCb + zh * sCh;
        Clo += zb * sCb + zh * sCh;
    }

    extern __shared__ uint32_t sm[];
    const int AST = 128 * 12;                 // one stage of one A array
    const int BST = NT * 12;
    uint32_t* AsHi = sm;                      // 2 stages
    uint32_t* AsLo = sm + 2 * AST;
    uint32_t* BsHi = sm + 4 * AST;
    uint32_t* BsLo = BsHi + 2 * BST;

    int tid = threadIdx.x;
    int w = tid >> 5, lane = tid & 31;
    int wm = w & 1, wn = w >> 1;              // warp grid 2 x 4
    int g = lane >> 2, tg = lane & 3;
    const int NTILES = NT / 32;

    int Keff = K;
    if (CKLIM) { int kl = bm + 128; Keff = (kl < K) ? kl : K; }
    int NCH = Keff >> 4;                      // 16 elements = 8 pairs per chunk

    float acc[4][NTILES][4];
    #pragma unroll
    for (int i = 0; i < 4; i++)
        #pragma unroll
        for (int j = 0; j < NTILES; j++)
            #pragma unroll
            for (int e = 0; e < 4; e++) acc[i][j][e] = 0.f;

    auto copy_chunk = [&](int c, int s) {
        int row = tid >> 1, seg = tid & 1;     // 128 rows x 2 segs of 4 uint32
        size_t ga = (size_t)(bm + row) * ldaP + c * 8 + seg * 4;
        uint32_t da = s * AST + row * 12 + seg * 4;
        cp16(smem_u32(AsHi + da), AhG + ga);
        cp16(smem_u32(AsLo + da), AlG + ga);
        if (NT == 128 || tid < 2 * NT) {
            size_t gb = (size_t)(bn + row) * ldbP + c * 8 + seg * 4;
            uint32_t db = s * BST + row * 12 + seg * 4;
            cp16(smem_u32(BsHi + db), BhG + gb);
            cp16(smem_u32(BsLo + db), BlG + gb);
        }
        CP_COMMIT();
    };

    copy_chunk(0, 0);
    if (NCH > 1) copy_chunk(1, 1);

    for (int c = 0; c < NCH; c++) {
        if (c + 1 < NCH) { CP_WAIT1(); } else { CP_WAIT0(); }
        __syncthreads();
        int s = c & 1;
        const uint32_t* AH = AsHi + s * AST;
        const uint32_t* AL = AsLo + s * AST;
        const uint32_t* BH = BsHi + s * BST;
        const uint32_t* BL = BsLo + s * BST;

        uint32_t ah[4][4], al[4][4];
        #pragma unroll
        for (int mt = 0; mt < 4; mt++) {
            int r0 = wm * 64 + mt * 16 + g;
            ah[mt][0] = AH[r0 * 12 + tg];
            ah[mt][1] = AH[(r0 + 8) * 12 + tg];
            ah[mt][2] = AH[r0 * 12 + tg + 4];
            ah[mt][3] = AH[(r0 + 8) * 12 + tg + 4];
            al[mt][0] = AL[r0 * 12 + tg];
            al[mt][1] = AL[(r0 + 8) * 12 + tg];
            al[mt][2] = AL[r0 * 12 + tg + 4];
            al[mt][3] = AL[(r0 + 8) * 12 + tg + 4];
        }
        uint32_t bh[NTILES][2], bl[NTILES][2];
        #pragma unroll
        for (int nt = 0; nt < NTILES; nt++) {
            int n0 = wn * (NT / 4) + nt * 8 + g;
            bh[nt][0] = BH[n0 * 12 + tg];
            bh[nt][1] = BH[n0 * 12 + tg + 4];
            bl[nt][0] = BL[n0 * 12 + tg];
            bl[nt][1] = BL[n0 * 12 + tg + 4];
        }
        #pragma unroll
        for (int mt = 0; mt < 4; mt++)
            #pragma unroll
            for (int nt = 0; nt < NTILES; nt++) {
                MMA16(acc[mt][nt], ah[mt], bl[nt]);
                MMA16(acc[mt][nt], al[mt], bh[nt]);
                MMA16(acc[mt][nt], ah[mt], bh[nt]);
            }
        __syncthreads();
        if (c + 2 < NCH) copy_chunk(c + 2, s);
    }

    // -------- epilogue --------
    #pragma unroll
    for (int mt = 0; mt < 4; mt++) {
        #pragma unroll
        for (int nt = 0; nt < NTILES; nt++) {
            int row0 = bm + wm * 64 + mt * 16 + g;
            int col  = bn + wn * (NT / 4) + nt * 8 + tg * 2;
            #pragma unroll
            for (int half = 0; half < 2; half++) {
                int row = row0 + half * 8;
                float v0 = acc[mt][nt][half * 2 + 0];
                float v1 = acc[mt][nt][half * 2 + 1];
                if (MODE == 1 || MODE == 2 || (MODE == 0 && bias)) {
                    float2 bv = *(const float2*)(bias + col);
                    v0 += bv.x; v1 += bv.y;
                }
                if (MODE == 1) {
                    float2 rr = *(const float2*)(R0 + (size_t)row * ldc + col);
                    v0 += rr.x; v1 += rr.y;
                }
                if (MODE == 2) {
                    v0 = 0.5f * v0 * (1.f + erff(v0 * 0.70710678118654752f));
                    v1 = 0.5f * v1 * (1.f + erff(v1 * 0.70710678118654752f));
                }
                if (MODE == 0 || MODE == 1) {
                    float2 o = {v0, v1};
                    *(float2*)(C + (size_t)row * ldc + col) = o;
                } else {
                    uint32_t hi, lo;
                    bsplit2(v0, v1, hi, lo);
                    size_t ci = (size_t)row * ldc + (col >> 1);
                    Chi[ci] = hi;
                    Clo[ci] = lo;
                }
            }
        }
    }
}

// ---------------- transpose + split: in[rows][cols] fp32 -> out[cols][rows/2] packed ----------------
__global__ void tsplit_kernel(const float* __restrict__ in,
                              uint32_t* __restrict__ ohi, uint32_t* __restrict__ olo,
                              int rows, int cols) {
    __shared__ float tile[32][33];
    int c0 = blockIdx.x * 32, r0 = blockIdx.y * 32;
    int x = threadIdx.x, y = threadIdx.y;
    float4 v = *(const float4*)(in + (size_t)(r0 + y) * cols + c0 + 4 * x);
    tile[y][4*x+0] = v.x; tile[y][4*x+1] = v.y; tile[y][4*x+2] = v.z; tile[y][4*x+3] = v.w;
    __syncthreads();
    int rowP = rows >> 1;
    uint32_t h0, l0, h1, l1;
    bsplit2(tile[4*x+0][y], tile[4*x+1][y], h0, l0);
    bsplit2(tile[4*x+2][y], tile[4*x+3][y], h1, l1);
    size_t ob = (size_t)(c0 + y) * rowP + (r0 >> 1) + 2 * x;
    *(uint2*)(ohi + ob) = make_uint2(h0, h1);
    *(uint2*)(olo + ob) = make_uint2(l0, l1);
}

// V inside fp32 qkv -> vt packed [(b*H+h)*64+d][t/2]
__global__ void vtrans_kernel(const float* __restrict__ qkv,
                              uint32_t* __restrict__ vthi, uint32_t* __restrict__ vtlo) {
    __shared__ float tile[32][33];
    int z = blockIdx.z, b = z >> 4, hh = z & 15;
    int t0 = blockIdx.x * 32, d0 = blockIdx.y * 32;
    int x = threadIdx.x, y = threadIdx.y;
    float4 v = *(const float4*)(qkv + (size_t)(b * Tc + t0 + y) * QS + 2 * Dc + hh * DHc + d0 + 4 * x);
    tile[y][4*x+0] = v.x; tile[y][4*x+1] = v.y; tile[y][4*x+2] = v.z; tile[y][4*x+3] = v.w;
    __syncthreads();
    uint32_t h0, l0, h1, l1;
    bsplit2(tile[4*x+0][y], tile[4*x+1][y], h0, l0);
    bsplit2(tile[4*x+2][y], tile[4*x+3][y], h1, l1);
    size_t ob = (size_t)(z * DHc + d0 + y) * 512 + (t0 >> 1) + 2 * x;
    *(uint2*)(vthi + ob) = make_uint2(h0, h1);
    *(uint2*)(vtlo + ob) = make_uint2(l0, l1);
}

// pack biases bq|bk|bv -> [L][3072]
__global__ void packbias_kernel(const float* __restrict__ bq,
                                const float* __restrict__ bk,
                                const float* __restrict__ bv,
                                float* __restrict__ out) {
    int l = blockIdx.y;
    int i = blockIdx.x * 256 + threadIdx.x;
    float v = (i < Dc) ? bq[l * Dc + i] : (i < 2 * Dc) ? bk[l * Dc + i - Dc] : bv[l * Dc + i - 2 * Dc];
    out[l * QS + i] = v;
}

// ---------------- block reductions ----------------
__device__ __forceinline__ float blockReduceSum(float v) {
    __shared__ float ws[32];
    int lane = threadIdx.x & 31, w = threadIdx.x >> 5;
    #pragma unroll
    for (int o = 16; o; o >>= 1) v += __shfl_down_sync(0xffffffffu, v, o);
    if (lane == 0) ws[w] = v;
    __syncthreads();
    int nw = blockDim.x >> 5;
    v = (threadIdx.x < nw) ? ws[threadIdx.x] : 0.f;
    if (w == 0) {
        #pragma unroll
        for (int o = 16; o; o >>= 1) v += __shfl_down_sync(0xffffffffu, v, o);
        if (lane == 0) ws[0] = v;
    }
    __syncthreads();
    float r = ws[0];
    __syncthreads();
    return r;
}
__device__ __forceinline__ float blockReduceMax(float v) {
    __shared__ float wm[32];
    int lane = threadIdx.x & 31, w = threadIdx.x >> 5;
    #pragma unroll
    for (int o = 16; o; o >>= 1) v = fmaxf(v, __shfl_down_sync(0xffffffffu, v, o));
    if (lane == 0) wm[w] = v;
    __syncthreads();
    int nw = blockDim.x >> 5;
    v = (threadIdx.x < nw) ? wm[threadIdx.x] : -FLT_MAX;
    if (w == 0) {
        #pragma unroll
        for (int o = 16; o; o >>= 1) v = fmaxf(v, __shfl_down_sync(0xffffffffu, v, o));
        if (lane == 0) wm[0] = v;
    }
    __syncthreads();
    float r = wm[0];
    __syncthreads();
    return r;
}

// ---------------- small kernels ----------------
__global__ void delta_kernel(const int* __restrict__ actions,
                             const float* __restrict__ action_emb,
                             const float* __restrict__ lie_w,
                             const float* __restrict__ lie_b,
                             float* __restrict__ delta) {
    int bt = blockIdx.x;
    __shared__ float emb[Dc];
    __shared__ float part[128];
    int a = actions[bt];
    const float* src = action_emb + (size_t)a * Dc;
    for (int i = threadIdx.x; i < Dc; i += blockDim.x) emb[i] = src[i];
    __syncthreads();
    int r = threadIdx.x & 31;
    int seg = threadIdx.x >> 5;
    float s = 0.f;
    int d0 = seg * 256;
    #pragma unroll 8
    for (int d = d0; d < d0 + 256; d++) s += emb[d] * lie_w[d * Rc + r];
    part[threadIdx.x] = s;
    __syncthreads();
    if (threadIdx.x < 32) {
        float v = part[threadIdx.x] + part[threadIdx.x + 32] +
                  part[threadIdx.x + 64] + part[threadIdx.x + 96];
        delta[(size_t)bt * Rc + threadIdx.x] = v + lie_b[threadIdx.x];
    }
}

__global__ void scan_kernel(const float* __restrict__ delta,
                            float* __restrict__ cosT, float* __restrict__ sinT) {
    int b = blockIdx.x / Rc, r = blockIdx.x % Rc;
    __shared__ float buf[2][Tc];
    int t = threadIdx.x;
    buf[0][t] = delta[((size_t)b * Tc + t) * Rc + r];
    __syncthreads();
    int src = 0;
    #pragma unroll
    for (int off = 1; off < Tc; off <<= 1) {
        float nv = buf[src][t];
        if (t >= off) nv += buf[src][t - off];
        buf[1 - src][t] = nv;
        src = 1 - src;
        __syncthreads();
    }
    float th = buf[src][t];
    size_t idx = ((size_t)b * Tc + t) * Rc + r;
    cosT[idx] = cosf(th);
    sinT[idx] = sinf(th);
}

__global__ void gather_kernel(const int* __restrict__ obs,
                              const float* __restrict__ emb,
                              float* __restrict__ x) {
    int bt = blockIdx.x;
    int o = obs[bt];
    const float4* s = (const float4*)(emb + (size_t)o * Dc);
    float4* d = (float4*)(x + (size_t)bt * Dc);
    d[threadIdx.x] = s[threadIdx.x];
}

// layernorm -> packed hi/lo output (feeds GEMM A)
__global__ void ln_kernel(const float* __restrict__ x,
                          const float* __restrict__ g,
                          const float* __restrict__ b,
                          uint32_t* __restrict__ ohi, uint32_t* __restrict__ olo) {
    int row = blockIdx.x;
    const float4* xr = (const float4*)(x + (size_t)row * Dc);
    float4 v = xr[threadIdx.x];
    float s = v.x + v.y + v.z + v.w;
    s = blockReduceSum(s);
    float mean = s * (1.f / Dc);
    float dx = v.x - mean, dy = v.y - mean, dz = v.z - mean, dw = v.w - mean;
    float s2 = dx*dx + dy*dy + dz*dz + dw*dw;
    s2 = blockReduceSum(s2);
    float rstd = rsqrtf(s2 * (1.f / Dc) + 1e-5f);
    float4 gv = ((const float4*)g)[threadIdx.x];
    float4 bv = ((const float4*)b)[threadIdx.x];
    float o0 = dx * rstd * gv.x + bv.x;
    float o1 = dy * rstd * gv.y + bv.y;
    float o2 = dz * rstd * gv.z + bv.z;
    float o3 = dw * rstd * gv.w + bv.w;
    uint32_t h0, l0, h1, l1;
    bsplit2(o0, o1, h0, l0);
    bsplit2(o2, o3, h1, l1);
    ((uint2*)(ohi + (size_t)row * 512))[threadIdx.x] = make_uint2(h0, h1);
    ((uint2*)(olo + (size_t)row * 512))[threadIdx.x] = make_uint2(l0, l1);
}

// rotate Q,K from fp32 qkv -> packed hi/lo arrays [bt][h*32 + r]
__global__ void rope_kernel(const float* __restrict__ cosT,
                            const float* __restrict__ sinT,
                            const float* __restrict__ QKV,
                            uint32_t* __restrict__ qhi, uint32_t* __restrict__ qlo,
                            uint32_t* __restrict__ khi, uint32_t* __restrict__ klo) {
    int idx = blockIdx.x * blockDim.x + threadIdx.x;
    if (idx >= Bc * Tc * Hc * Rc) return;
    int r = idx & 31;
    int hh = (idx >> 5) & 15;
    int bt = idx >> 9;
    float c = cosT[(size_t)bt * Rc + r];
    float s = sinT[(size_t)bt * Rc + r];
    size_t base = (size_t)bt * QS + hh * DHc + 2 * r;
    float2 q = *(const float2*)(QKV + base);
    float2 k = *(const float2*)(QKV + base + Dc);
    float qx = c * q.x - s * q.y, qy = s * q.x + c * q.y;
    float kx = c * k.x - s * k.y, ky = s * k.x + c * k.y;
    size_t pi = (size_t)bt * 512 + hh * 32 + r;
    uint32_t hi, lo;
    bsplit2(qx, qy, hi, lo);  qhi[pi] = hi; qlo[pi] = lo;
    bsplit2(kx, ky, hi, lo);  khi[pi] = hi; klo[pi] = lo;
}

// causal softmax: fp32 scores in -> packed hi/lo out (zero-filled to end of diag tile)
__global__ void softmax_kernel(const float* __restrict__ scores,
                               uint32_t* __restrict__ ohi, uint32_t* __restrict__ olo) {
    int row = blockIdx.x;
    int t = row & (Tc - 1);
    const float* p = scores + (size_t)row * Tc;
    int valid = t + 1;
    int lastStore = ((t >> 7) + 1) << 7;
    int base = threadIdx.x * 4;
    float vals[4] = {0.f, 0.f, 0.f, 0.f};
    if (base < valid) {
        float4 v = ((const float4*)p)[threadIdx.x];
        vals[0] = v.x; vals[1] = v.y; vals[2] = v.z; vals[3] = v.w;
    }
    float m = -FLT_MAX;
    #pragma unroll
    for (int c = 0; c < 4; c++) {
        vals[c] = (base + c < valid) ? vals[c] * 0.125f : -FLT_MAX;
        m = fmaxf(m, vals[c]);
    }
    m = blockReduceMax(m);
    float s = 0.f;
    #pragma unroll
    for (int c = 0; c < 4; c++) {
        vals[c] = (base + c < valid) ? __expf(vals[c] - m) : 0.f;
        s += vals[c];
    }
    s = blockReduceSum(s);
    float inv = 1.f / s;
    if (base < lastStore) {
        uint32_t h0, l0, h1, l1;
        bsplit2(vals[0] * inv, vals[1] * inv, h0, l0);
        bsplit2(vals[2] * inv, vals[3] * inv, h1, l1);
        ((uint2*)(ohi + (size_t)row * 512))[threadIdx.x] = make_uint2(h0, h1);
        ((uint2*)(olo + (size_t)row * 512))[threadIdx.x] = make_uint2(l0, l1);
    }
}

// ---------------- host launcher ----------------
template<typename T>
static T* symaddr(const void* sym) {
    void* p = nullptr;
    cudaGetSymbolAddress(&p, sym);
    return (T*)p;
}

extern "C" void kernel_launch(void* const* d_in, const int* in_sizes, int n_in,
                              void* d_out, int out_size) {
    const int*   actions      = (const int*)  d_in[0];
    const int*   observations = (const int*)  d_in[1];
    const float* action_emb   = (const float*)d_in[2];
    const float* obs_emb      = (const float*)d_in[3];
    const float* lie_w        = (const float*)d_in[4];
    const float* lie_b        = (const float*)d_in[5];
    const float* Wq  = (const float*)d_in[6];
    const float* bq  = (const float*)d_in[7];
    const float* Wk  = (const float*)d_in[8];
    const float* bk  = (const float*)d_in[9];
    const float* Wv  = (const float*)d_in[10];
    const float* bv  = (const float*)d_in[11];
    const float* Wo  = (const float*)d_in[12];
    const float* bo  = (const float*)d_in[13];
    const float* ln1_g = (const float*)d_in[14];
    const float* ln1_b = (const float*)d_in[15];
    const float* ln2_g = (const float*)d_in[16];
    const float* ln2_b = (const float*)d_in[17];
    const float* w1  = (const float*)d_in[18];
    const float* b1  = (const float*)d_in[19];
    const float* w2  = (const float*)d_in[20];
    const float* b2  = (const float*)d_in[21];
    const float* out_g   = (const float*)d_in[22];
    const float* out_bln = (const float*)d_in[23];
    const float* out_w   = (const float*)d_in[24];
    const float* out_b   = (const float*)d_in[25];
    (void)in_sizes; (void)n_in; (void)out_size;

    float* dlt  = symaddr<float>(g_delta);
    float* cT   = symaddr<float>(g_cos);
    float* sT   = symaddr<float>(g_sin);
    float* x    = symaddr<float>(g_x);
    float* qkv  = symaddr<float>(g_qkv);
    float* sc   = symaddr<float>(g_sc);
    float* bqkv = symaddr<float>(g_bqkv);
    uint32_t* hhi = symaddr<uint32_t>(g_hhi);
    uint32_t* hlo = symaddr<uint32_t>(g_hlo);
    uint32_t* qhi = symaddr<uint32_t>(g_qhi);
    uint32_t* qlo = symaddr<uint32_t>(g_qlo);
    uint32_t* khi = symaddr<uint32_t>(g_khi);
    uint32_t* klo = symaddr<uint32_t>(g_klo);
    uint32_t* vthi = symaddr<uint32_t>(g_vthi);
    uint32_t* vtlo = symaddr<uint32_t>(g_vtlo);
    uint32_t* schi = symaddr<uint32_t>(g_schi);
    uint32_t* sclo = symaddr<uint32_t>(g_sclo);
    uint32_t* ohi = symaddr<uint32_t>(g_ohi);
    uint32_t* olo = symaddr<uint32_t>(g_olo);
    uint32_t* ffhi = symaddr<uint32_t>(g_ffhi);
    uint32_t* fflo = symaddr<uint32_t>(g_fflo);
    uint32_t* whi = symaddr<uint32_t>(g_whi);
    uint32_t* wlo = symaddr<uint32_t>(g_wlo);

    const int SMB128 = (4 * 128 * 12 + 4 * 128 * 12) * 4;  // 49152
    const int SMB64  = (4 * 128 * 12 + 4 * 64 * 12) * 4;   // 36864

    cudaFuncSetAttribute(mma_gemm<128,0,false,false>, cudaFuncAttributeMaxDynamicSharedMemorySize, SMB128);
    cudaFuncSetAttribute(mma_gemm<128,1,false,false>, cudaFuncAttributeMaxDynamicSharedMemorySize, SMB128);
    cudaFuncSetAttribute(mma_gemm<128,2,false,false>, cudaFuncAttributeMaxDynamicSharedMemorySize, SMB128);
    cudaFuncSetAttribute(mma_gemm<128,0,true,false>,  cudaFuncAttributeMaxDynamicSharedMemorySize, SMB128);
    cudaFuncSetAttribute(mma_gemm<64,3,false,true>,   cudaFuncAttributeMaxDynamicSharedMemorySize, SMB64);

    dim3 tb(8, 32);
    // weight transpose + bf16 split (once per replay)
    for (int l = 0; l < Lc; l++) {
        size_t wb = WPL(l);
        tsplit_kernel<<<dim3(32, 32), tb>>>(Wq + (size_t)l*DD, whi + wb,              wlo + wb,              Dc, Dc);
        tsplit_kernel<<<dim3(32, 32), tb>>>(Wk + (size_t)l*DD, whi + wb + 1024*512,   wlo + wb + 1024*512,   Dc, Dc);
        tsplit_kernel<<<dim3(32, 32), tb>>>(Wv + (size_t)l*DD, whi + wb + 2048*512,   wlo + wb + 2048*512,   Dc, Dc);
        tsplit_kernel<<<dim3(32, 32), tb>>>(Wo + (size_t)l*DD, whi + wb + P_WO,       wlo + wb + P_WO,       Dc, Dc);
        tsplit_kernel<<<dim3(128,32), tb>>>(w1 + (size_t)l*Dc*FFc, whi + wb + P_W1,   wlo + wb + P_W1,       Dc, FFc);
        tsplit_kernel<<<dim3(32,128), tb>>>(w2 + (size_t)l*FFc*Dc, whi + wb + P_W2,   wlo + wb + P_W2,       FFc, Dc);
    }
    tsplit_kernel<<<dim3(512, 32), tb>>>(out_w, whi + P_OUT, wlo + P_OUT, Dc, OVc);
    packbias_kernel<<<dim3(12, Lc), 256>>>(bq, bk, bv, bqkv);

    // position state
    delta_kernel<<<BT, 128>>>(actions, action_emb, lie_w, lie_b, dlt);
    scan_kernel<<<Bc * Rc, Tc>>>(dlt, cT, sT);
    gather_kernel<<<BT, 256>>>(observations, obs_emb, x);

    for (int l = 0; l < Lc; l++) {
        size_t wb = WPL(l);
        ln_kernel<<<BT, 256>>>(x, ln1_g + l * Dc, ln1_b + l * Dc, hhi, hlo);

        // fused QKV -> fp32 qkv
        dim3 gQ(QS / 128, BT / 128, 1);
        mma_gemm<128,0,false,false><<<gQ, 256, SMB128>>>(hhi, hlo, whi + wb, wlo + wb,
            bqkv + l*QS, nullptr, qkv, nullptr, nullptr,
            BT, QS, Dc, 512, 512, QS, 1, 0,0,0,0,0,0);

        rope_kernel<<<(Bc*Tc*Hc*Rc) / 256, 256>>>(cT, sT, qkv, qhi, qlo, khi, klo);
        vtrans_kernel<<<dim3(Tc/32, 2, Bc*Hc), tb>>>(qkv, vthi, vtlo);

        // scores = Qr @ Kr^T (causal tiles only) -> fp32 sc
        dim3 gS(Tc / 128, Tc / 128, Bc * Hc);
        mma_gemm<128,0,true,false><<<gS, 256, SMB128>>>(qhi, qlo, khi, klo,
            nullptr, nullptr, sc, nullptr, nullptr,
            Tc, Tc, DHc, 512, 512, Tc,
            Hc, (long long)Tc*512, 32, (long long)Tc*512, 32,
                (long long)Hc*Tc*Tc, (long long)Tc*Tc);

        softmax_kernel<<<Bc * Hc * Tc, 256>>>(sc, schi, sclo);

        // o = attn @ V (K clamped) -> packed o
        dim3 gA(1, Tc / 128, Bc * Hc);
        mma_gemm<64,3,false,true><<<gA, 256, SMB64>>>(schi, sclo, vthi, vtlo,
            nullptr, nullptr, nullptr, ohi, olo,
            Tc, DHc, Tc, 512, 512, 512,
            Hc, (long long)Hc*Tc*512, (long long)Tc*512,
                (long long)Hc*DHc*512, (long long)DHc*512,
                (long long)Tc*512, 32);

        // x = x + o @ Wo + bo
        dim3 gP(Dc / 128, BT / 128, 1);
        mma_gemm<128,1,false,false><<<gP, 256, SMB128>>>(ohi, olo, whi + wb + P_WO, wlo + wb + P_WO,
            bo + l*Dc, x, x, nullptr, nullptr,
            BT, Dc, Dc, 512, 512, Dc, 1, 0,0,0,0,0,0);

        ln_kernel<<<BT, 256>>>(x, ln2_g + l * Dc, ln2_b + l * Dc, hhi, hlo);

        // FFN1: gelu -> packed ff
        dim3 gF1(FFc / 128, BT / 128, 1);
        mma_gemm<128,2,false,false><<<gF1, 256, SMB128>>>(hhi, hlo, whi + wb + P_W1, wlo + wb + P_W1,
            b1 + l*FFc, nullptr, nullptr, ffhi, fflo,
            BT, FFc, Dc, 512, 512, 2048, 1, 0,0,0,0,0,0);

        // FFN2: residual -> x
        dim3 gF2(Dc / 128, BT / 128, 1);
        mma_gemm<128,1,false,false><<<gF2, 256, SMB128>>>(ffhi, fflo, whi + wb + P_W2, wlo + wb + P_W2,
            b2 + l*Dc, x, x, nullptr, nullptr,
            BT, Dc, FFc, 2048, 2048, Dc, 1, 0,0,0,0,0,0);
    }

    ln_kernel<<<BT, 256>>>(x, out_g, out_bln, hhi, hlo);
    dim3 gO(OVc / 128, BT / 128, 1);
    mma_gemm<128,0,false,false><<<gO, 256, SMB128>>>(hhi, hlo, whi + P_OUT, wlo + P_OUT,
        out_b, nullptr, (float*)d_out, nullptr, nullptr,
        BT, OVc, Dc, 512, 512, OVc, 1, 0,0,0,0,0,0);
}